// round 16
// baseline (speedup 1.0000x reference)
#include <cuda_runtime.h>
#include <cuda_fp16.h>
#include <cstdint>

#define N_NODES   50000
#define F_DIM     256
#define N_EDGES   800000
#define PAD_M     50048          // 391 * 128

#define SCAN_B    256
#define SCAN_NB   ((N_NODES + SCAN_B - 1) / SCAN_B)   // 196

#define PREPW_B   64

// Scratch (__device__ globals; no allocation allowed)
__device__ __half g_yh[(size_t)N_NODES * F_DIM];  // Y = X @ W^T, fp16
__device__ __half g_wh[F_DIM * F_DIM];            // W in fp16
__device__ int    g_cnt[N_NODES];
__device__ int    g_off[N_NODES + 1];
__device__ int    g_rank[N_EDGES];                // edge rank within its row
__device__ unsigned long long g_scan_pkt[SCAN_NB];
__device__ int2   g_cv[N_EDGES];                  // packed (col, val-bits)

// ---------------------------------------------------------------------------
// cp.async helpers
// ---------------------------------------------------------------------------
__device__ __forceinline__ void cp_async16(uint32_t smem_addr, const void* gptr,
                                           int src_size) {
    asm volatile("cp.async.cg.shared.global [%0], [%1], 16, %2;"
                 :: "r"(smem_addr), "l"(gptr), "r"(src_size));
}
__device__ __forceinline__ void cp_commit() { asm volatile("cp.async.commit_group;"); }
template <int N>
__device__ __forceinline__ void cp_wait() {
    asm volatile("cp.async.wait_group %0;" :: "n"(N));
}

// ---------------------------------------------------------------------------
// hist (stores per-edge rank)
// ---------------------------------------------------------------------------
__global__ __launch_bounds__(256)
void k_hist(const int* __restrict__ edge_row) {
    int e = blockIdx.x * blockDim.x + threadIdx.x;
    if (e < N_EDGES) {
        int r = edge_row[e];
        g_rank[e] = atomicAdd(&g_cnt[r], 1);
    }
}

// ---------------------------------------------------------------------------
// prep: W -> fp16 only (X conversion folded into the GEMM)
// ---------------------------------------------------------------------------
__global__ __launch_bounds__(256)
void k_prep(const float* __restrict__ W) {
    int i = blockIdx.x * 256 + threadIdx.x;        // float4 index, 16384 total
    float4 v = reinterpret_cast<const float4*>(W)[i];
    __half2 h0 = __floats2half2_rn(v.x, v.y);
    __half2 h1 = __floats2half2_rn(v.z, v.w);
    reinterpret_cast<__half2*>(g_wh)[2 * i]     = h0;
    reinterpret_cast<__half2*>(g_wh)[2 * i + 1] = h1;
}

// ---------------------------------------------------------------------------
// Single-pass decoupled-lookback scan
// ---------------------------------------------------------------------------
__global__ void k_scan_fused() {
    __shared__ int warp_sums[8];
    __shared__ int s_base;
    const int b    = blockIdx.x;
    const int t    = threadIdx.x;
    const int lane = t & 31;
    const int w    = t >> 5;
    const int i    = b * SCAN_B + t;

    int v = (i < N_NODES) ? g_cnt[i] : 0;

    int inc = v;
#pragma unroll
    for (int d = 1; d < 32; d <<= 1) {
        int tt = __shfl_up_sync(0xffffffffu, inc, d);
        if (lane >= d) inc += tt;
    }
    if (lane == 31) warp_sums[w] = inc;
    __syncthreads();
    if (w == 0) {
        int ws = (lane < 8) ? warp_sums[lane] : 0;
#pragma unroll
        for (int d = 1; d < 8; d <<= 1) {
            int tt = __shfl_up_sync(0xffffffffu, ws, d);
            if (lane >= d) ws += tt;
        }
        if (lane < 8) warp_sums[lane] = ws;
    }
    __syncthreads();
    int excl  = inc - v + ((w > 0) ? warp_sums[w - 1] : 0);
    int total = warp_sums[7];

    if (t == 0) {
        if (b == 0) {
            atomicExch(&g_scan_pkt[0], (2ULL << 62) | (unsigned)total);
            s_base = 0;
        } else {
            atomicExch(&g_scan_pkt[b], (1ULL << 62) | (unsigned)total);
            int run = 0;
            int j = b - 1;
            while (true) {
                unsigned long long p;
                while (((p = atomicAdd(&g_scan_pkt[j], 0ULL)) >> 62) == 0) {}
                run += (int)(p & 0xFFFFFFFFULL);
                if ((p >> 62) == 2ULL) break;
                j--;
            }
            atomicExch(&g_scan_pkt[b], (2ULL << 62) | (unsigned)(run + total));
            s_base = run;
        }
    }
    __syncthreads();
    int base = s_base;
    if (i < N_NODES) g_off[i] = base + excl;
    if (i == N_NODES - 1) g_off[N_NODES] = N_EDGES;
}

// ---------------------------------------------------------------------------
// Scatter: atomic-free, position = off[row] + rank
// ---------------------------------------------------------------------------
__global__ __launch_bounds__(256)
void k_scatter(const int*   __restrict__ edge_row,
               const int*   __restrict__ edge_col,
               const float* __restrict__ edge_val) {
    int e = blockIdx.x * blockDim.x + threadIdx.x;
    if (e < N_EDGES) {
        int r = edge_row[e];
        int p = g_off[r] + g_rank[e];
        g_cv[p] = make_int2(edge_col[e], __float_as_int(edge_val[e]));
    }
}

// ---------------------------------------------------------------------------
// GEMM  Y[m,n] = sum_k X[m,k]*W[n,k]  (fp16 MMA, fp32 acc)
// CTA 128x128, BK=32, 8 warps 4(M) x 2(N), 256 threads, 2 CTAs/SM.
// cp.async 2-deep pipeline. A staged as RAW FP32 (no prep pass); converted
// to fp16 at fragment-load time (LDS.64 + cvt) — bit-identical to prep_x.
// Dynamic smem: A 2x18KB fp32 + W 2x10KB fp16 = 56.25KB.
// ---------------------------------------------------------------------------
#define BM 128
#define BN 128
#define BK 32
#define LDS_KF 36               // fp32 A row stride (pad 4)
#define LDS_K  40               // fp16 W row stride (pad 8)
#define KTILES (F_DIM / BK)     // 8

#define SMEM_A_BYTES (2 * BM * LDS_KF * 4)            // 36864
#define SMEM_W_BYTES (2 * BN * LDS_K * 2)             // 20480
#define SMEM_GEMM    (SMEM_A_BYTES + SMEM_W_BYTES)    // 57344

__device__ __forceinline__ void mma_f16(float* c, const uint32_t* a, const uint32_t* b) {
    asm volatile(
        "mma.sync.aligned.m16n8k16.row.col.f32.f16.f16.f32 "
        "{%0,%1,%2,%3}, {%4,%5,%6,%7}, {%8,%9}, {%0,%1,%2,%3};"
        : "+f"(c[0]), "+f"(c[1]), "+f"(c[2]), "+f"(c[3])
        : "r"(a[0]), "r"(a[1]), "r"(a[2]), "r"(a[3]), "r"(b[0]), "r"(b[1]));
}

__device__ __forceinline__ uint32_t f2h2(float2 f) {
    __half2 h = __floats2half2_rn(f.x, f.y);
    return *reinterpret_cast<uint32_t*>(&h);
}

__global__ __launch_bounds__(256, 2)
void gemm_kernel(const float* __restrict__ X) {
    extern __shared__ char smem[];
    float*  As = reinterpret_cast<float*>(smem);                     // [2][BM][LDS_KF]
    __half* Ws = reinterpret_cast<__half*>(smem + SMEM_A_BYTES);     // [2][BN][LDS_K]

    const int t    = threadIdx.x;
    const int lane = t & 31;
    const int wid  = t >> 5;
    const int wm   = wid & 3;
    const int wn   = wid >> 2;
    const int g    = lane >> 2;
    const int tid4 = lane & 3;

    const int m0 = blockIdx.x * BM;
    const int n0 = blockIdx.y * BN;

    // ---- staging geometry ----
    // A: 128 rows x 32 floats = 1024 x 16B chunks, 4 per thread
    int rowA[4], c4A[4];
    const float* xsrc[4];
    int xsz[4];
    uint32_t adst[2][4];
#pragma unroll
    for (int i = 0; i < 4; i++) {
        int idx = t + i * 256;            // 0..1023
        rowA[i] = idx >> 3;               // 0..127
        c4A[i]  = idx & 7;                // 0..7 (4 floats each)
        int m   = m0 + rowA[i];
        bool ok = (m < N_NODES);
        xsz[i]  = ok ? 16 : 0;
        xsrc[i] = X + (size_t)(ok ? m : 0) * F_DIM + c4A[i] * 4;
#pragma unroll
        for (int bu = 0; bu < 2; bu++)
            adst[bu][i] = (uint32_t)__cvta_generic_to_shared(
                &As[(bu * BM + rowA[i]) * LDS_KF + c4A[i] * 4]);
    }
    // W: 128 rows x 32 halfs = 512 x 16B chunks, 2 per thread
    int rowW[2], c8W[2];
    const __half* wsrc[2];
    uint32_t wdst[2][2];
#pragma unroll
    for (int i = 0; i < 2; i++) {
        int idx = t + i * 256;
        rowW[i] = idx >> 2;
        c8W[i]  = idx & 3;
        wsrc[i] = g_wh + (size_t)(n0 + rowW[i]) * F_DIM + c8W[i] * 8;
#pragma unroll
        for (int bu = 0; bu < 2; bu++)
            wdst[bu][i] = (uint32_t)__cvta_generic_to_shared(
                &Ws[(bu * BN + rowW[i]) * LDS_K + c8W[i] * 8]);
    }

    // ---- prologue: issue tiles 0 and 1 ----
#pragma unroll
    for (int kt = 0; kt < 2; kt++) {
        int koff = kt * BK;
#pragma unroll
        for (int i = 0; i < 4; i++)
            cp_async16(adst[kt][i], xsrc[i] + koff, xsz[i]);
#pragma unroll
        for (int i = 0; i < 2; i++)
            cp_async16(wdst[kt][i], wsrc[i] + koff, 16);
        cp_commit();
    }

    float acc[2][8][4];
#pragma unroll
    for (int i = 0; i < 2; i++)
#pragma unroll
        for (int j = 0; j < 8; j++)
#pragma unroll
            for (int k = 0; k < 4; k++) acc[i][j][k] = 0.f;

#pragma unroll
    for (int kt = 0; kt < KTILES; kt++) {
        const int buf = kt & 1;
        cp_wait<1>();
        __syncthreads();

#pragma unroll
        for (int ks = 0; ks < 2; ks++) {
            int kb = ks * 16;
            uint32_t a[2][4];
#pragma unroll
            for (int mi = 0; mi < 2; mi++) {
                int r = wm * 32 + mi * 16;
                const float* base0 = &As[(buf * BM + r + g    ) * LDS_KF];
                const float* base1 = &As[(buf * BM + r + g + 8) * LDS_KF];
                a[mi][0] = f2h2(*reinterpret_cast<const float2*>(base0 + kb + 2 * tid4));
                a[mi][1] = f2h2(*reinterpret_cast<const float2*>(base1 + kb + 2 * tid4));
                a[mi][2] = f2h2(*reinterpret_cast<const float2*>(base0 + kb + 2 * tid4 + 8));
                a[mi][3] = f2h2(*reinterpret_cast<const float2*>(base1 + kb + 2 * tid4 + 8));
            }
            uint32_t b[8][2];
#pragma unroll
            for (int ni = 0; ni < 8; ni++) {
                int n = wn * 64 + ni * 8 + g;
                const __half* wb = &Ws[(buf * BN + n) * LDS_K];
                b[ni][0] = *reinterpret_cast<const uint32_t*>(wb + kb + 2 * tid4);
                b[ni][1] = *reinterpret_cast<const uint32_t*>(wb + kb + 2 * tid4 + 8);
            }
#pragma unroll
            for (int mi = 0; mi < 2; mi++)
#pragma unroll
                for (int ni = 0; ni < 8; ni++)
                    mma_f16(acc[mi][ni], a[mi], b[ni]);
        }
        __syncthreads();

        if (kt + 2 < KTILES) {
            int koff = (kt + 2) * BK;
#pragma unroll
            for (int i = 0; i < 4; i++)
                cp_async16(adst[buf][i], xsrc[i] + koff, xsz[i]);
#pragma unroll
            for (int i = 0; i < 2; i++)
                cp_async16(wdst[buf][i], wsrc[i] + koff, 16);
            cp_commit();
        } else {
            cp_commit();
        }
    }

    // store Y as fp16
#pragma unroll
    for (int mi = 0; mi < 2; mi++) {
        int r_base = m0 + wm * 32 + mi * 16;
#pragma unroll
        for (int ni = 0; ni < 8; ni++) {
            int col = n0 + wn * 64 + ni * 8 + 2 * tid4;
            int r0 = r_base + g;
            int r1 = r_base + g + 8;
            if (r0 < N_NODES) {
                __half2 h = __floats2half2_rn(acc[mi][ni][0], acc[mi][ni][1]);
                *reinterpret_cast<__half2*>(g_yh + (size_t)r0 * F_DIM + col) = h;
            }
            if (r1 < N_NODES) {
                __half2 h = __floats2half2_rn(acc[mi][ni][2], acc[mi][ni][3]);
                *reinterpret_cast<__half2*>(g_yh + (size_t)r1 * F_DIM + col) = h;
            }
        }
    }
}

// ---------------------------------------------------------------------------
// Gather: out[r] = sum_e val_e * Y[col_e] + b.  One warp per row. FFMA2.
// R13-proven form (4-deep unroll, launch_bounds(256,6)).
// ---------------------------------------------------------------------------
__device__ __forceinline__ void fma8_x2(unsigned long long* acc, uint4 u,
                                        unsigned long long v2) {
    const __half2* h = reinterpret_cast<const __half2*>(&u);
#pragma unroll
    for (int q = 0; q < 4; q++) {
        float2 f = __half22float2(h[q]);
        unsigned long long fu;
        asm("mov.b64 %0, {%1, %2};" : "=l"(fu) : "f"(f.x), "f"(f.y));
        asm("fma.rn.f32x2 %0, %1, %2, %0;" : "+l"(acc[q]) : "l"(fu), "l"(v2));
    }
}

__global__ __launch_bounds__(256, 6)
void k_gather(const float* __restrict__ bias, float* __restrict__ out) {
    int r    = (blockIdx.x * blockDim.x + threadIdx.x) >> 5;
    int lane = threadIdx.x & 31;
    if (r >= N_NODES) return;

    unsigned long long acc[4];
#pragma unroll
    for (int q = 0; q < 4; q++) acc[q] = 0ULL;

    int start = g_off[r];
    int end   = g_off[r + 1];

    for (int base = start; base < end; base += 32) {
        int n = min(32, end - base);
        int   col = 0;
        float val = 0.f;
        if (lane < n) {
            int2 cv = __ldg(&g_cv[base + lane]);
            col = cv.x;
            val = __int_as_float(cv.y);
        }
        int j = 0;
        for (; j + 4 <= n; j += 4) {
            int   c0 = __shfl_sync(0xffffffffu, col, j);
            int   c1 = __shfl_sync(0xffffffffu, col, j + 1);
            int   c2 = __shfl_sync(0xffffffffu, col, j + 2);
            int   c3 = __shfl_sync(0xffffffffu, col, j + 3);
            float v0 = __shfl_sync(0xffffffffu, val, j);
            float v1 = __shfl_sync(0xffffffffu, val, j + 1);
            float v2 = __shfl_sync(0xffffffffu, val, j + 2);
            float v3 = __shfl_sync(0xffffffffu, val, j + 3);
            uint4 u0 = __ldg(reinterpret_cast<const uint4*>(g_yh + (size_t)c0 * F_DIM) + lane);
            uint4 u1 = __ldg(reinterpret_cast<const uint4*>(g_yh + (size_t)c1 * F_DIM) + lane);
            uint4 u2 = __ldg(reinterpret_cast<const uint4*>(g_yh + (size_t)c2 * F_DIM) + lane);
            uint4 u3 = __ldg(reinterpret_cast<const uint4*>(g_yh + (size_t)c3 * F_DIM) + lane);
            unsigned long long p0, p1, p2, p3;
            asm("mov.b64 %0, {%1, %1};" : "=l"(p0) : "f"(v0));
            asm("mov.b64 %0, {%1, %1};" : "=l"(p1) : "f"(v1));
            asm("mov.b64 %0, {%1, %1};" : "=l"(p2) : "f"(v2));
            asm("mov.b64 %0, {%1, %1};" : "=l"(p3) : "f"(v3));
            fma8_x2(acc, u0, p0);
            fma8_x2(acc, u1, p1);
            fma8_x2(acc, u2, p2);
            fma8_x2(acc, u3, p3);
        }
        for (; j < n; j++) {
            int   c = __shfl_sync(0xffffffffu, col, j);
            float v = __shfl_sync(0xffffffffu, val, j);
            uint4 u = __ldg(reinterpret_cast<const uint4*>(g_yh + (size_t)c * F_DIM) + lane);
            unsigned long long p;
            asm("mov.b64 %0, {%1, %1};" : "=l"(p) : "f"(v));
            fma8_x2(acc, u, p);
        }
    }

    float a[8];
#pragma unroll
    for (int q = 0; q < 4; q++) {
        float lo, hi;
        asm("mov.b64 {%0, %1}, %2;" : "=f"(lo), "=f"(hi) : "l"(acc[q]));
        a[2 * q]     = lo;
        a[2 * q + 1] = hi;
    }
    const float4* bp = reinterpret_cast<const float4*>(bias + lane * 8);
    float4 b0 = __ldg(bp);
    float4 b1 = __ldg(bp + 1);
    float4 o0 = make_float4(a[0] + b0.x, a[1] + b0.y, a[2] + b0.z, a[3] + b0.w);
    float4 o1 = make_float4(a[4] + b1.x, a[5] + b1.y, a[6] + b1.z, a[7] + b1.w);
    float4* orow = reinterpret_cast<float4*>(out + (size_t)r * F_DIM + lane * 8);
    orow[0] = o0;
    orow[1] = o1;
}

// ---------------------------------------------------------------------------
// Launch: fork/join (R13-proven structure), prep_x eliminated
//   chain A (default stream): memsets -> hist -> scan -> scatter
//   chain B (s2):             prep_w -> gemm (reads fp32 X directly)
//   join -> gather
// ---------------------------------------------------------------------------
extern "C" void kernel_launch(void* const* d_in, const int* in_sizes, int n_in,
                              void* d_out, int out_size) {
    const float* x        = (const float*)d_in[0];
    const int*   edge_row = (const int*)  d_in[1];
    const int*   edge_col = (const int*)  d_in[2];
    const float* edge_val = (const float*)d_in[3];
    const float* W        = (const float*)d_in[4];
    const float* b        = (const float*)d_in[5];
    float*       out      = (float*)d_out;

    static cudaStream_t s2 = nullptr;
    static cudaEvent_t  ev_fork = nullptr, ev_join = nullptr;
    if (s2 == nullptr) {
        cudaStreamCreateWithFlags(&s2, cudaStreamNonBlocking);
        cudaEventCreateWithFlags(&ev_fork, cudaEventDisableTiming);
        cudaEventCreateWithFlags(&ev_join, cudaEventDisableTiming);
        cudaFuncSetAttribute(gemm_kernel,
                             cudaFuncAttributeMaxDynamicSharedMemorySize, SMEM_GEMM);
    }

    // ---- fork ----
    cudaEventRecord(ev_fork, 0);
    cudaStreamWaitEvent(s2, ev_fork, 0);

    // ---- chain A: CSR build (default stream) ----
    void* cnt_ptr = nullptr;
    cudaGetSymbolAddress(&cnt_ptr, g_cnt);
    cudaMemsetAsync(cnt_ptr, 0, N_NODES * sizeof(int));
    void* pkt_ptr = nullptr;
    cudaGetSymbolAddress(&pkt_ptr, g_scan_pkt);
    cudaMemsetAsync(pkt_ptr, 0, SCAN_NB * sizeof(unsigned long long));
    k_hist<<<(N_EDGES + 255) / 256, 256>>>(edge_row);
    k_scan_fused<<<SCAN_NB, SCAN_B>>>();
    k_scatter<<<(N_EDGES + 255) / 256, 256>>>(edge_row, edge_col, edge_val);

    // ---- chain B: prep_w + GEMM (s2) ----
    k_prep<<<PREPW_B, 256, 0, s2>>>(W);
    {
        dim3 grid(PAD_M / BM, F_DIM / BN);   // 391 x 2
        gemm_kernel<<<grid, 256, SMEM_GEMM, s2>>>(x);
    }

    // ---- join ----
    cudaEventRecord(ev_join, s2);
    cudaStreamWaitEvent(0, ev_join, 0);

    // ---- gather (needs scatter + gemm) ----
    k_gather<<<(N_NODES * 32 + 255) / 256, 256>>>(b, out);
}

// round 17
// speedup vs baseline: 1.0286x; 1.0286x over previous
#include <cuda_runtime.h>
#include <cuda_fp16.h>
#include <cstdint>

#define N_NODES   50000
#define F_DIM     256
#define N_EDGES   800000
#define PAD_M     50048          // 391 * 128

#define SCAN_B    256
#define SCAN_NB   ((N_NODES + SCAN_B - 1) / SCAN_B)   // 196

// prep roles: prep_w | prep_x
#define PREPW_B   64
#define PREPX_B   6250
#define PREP_BLOCKS (PREPW_B + PREPX_B)

// Scratch (__device__ globals; no allocation allowed)
__device__ __half g_yh[(size_t)N_NODES * F_DIM];  // Y = X @ W^T, fp16
__device__ __half g_xh[(size_t)N_NODES * F_DIM];  // X in fp16
__device__ __half g_wh[F_DIM * F_DIM];            // W in fp16
__device__ int    g_cnt[N_NODES];
__device__ int    g_off[N_NODES + 1];
__device__ int    g_rank[N_EDGES];                // edge rank within its row
__device__ unsigned long long g_scan_pkt[SCAN_NB];
__device__ int2   g_cv[N_EDGES];                  // packed (col, val-bits)

// ---------------------------------------------------------------------------
// cp.async helpers
// ---------------------------------------------------------------------------
__device__ __forceinline__ void cp_async16(uint32_t smem_addr, const void* gptr,
                                           int src_size) {
    asm volatile("cp.async.cg.shared.global [%0], [%1], 16, %2;"
                 :: "r"(smem_addr), "l"(gptr), "r"(src_size));
}
__device__ __forceinline__ void cp_commit() { asm volatile("cp.async.commit_group;"); }
template <int N>
__device__ __forceinline__ void cp_wait() {
    asm volatile("cp.async.wait_group %0;" :: "n"(N));
}

// ---------------------------------------------------------------------------
// hist (stores per-edge rank)
// ---------------------------------------------------------------------------
__global__ __launch_bounds__(256)
void k_hist(const int* __restrict__ edge_row) {
    int e = blockIdx.x * blockDim.x + threadIdx.x;
    if (e < N_EDGES) {
        int r = edge_row[e];
        g_rank[e] = atomicAdd(&g_cnt[r], 1);
    }
}

// ---------------------------------------------------------------------------
// prep_w | prep_x
// ---------------------------------------------------------------------------
__global__ __launch_bounds__(256)
void k_prep(const float* __restrict__ W, const float* __restrict__ X) {
    int bid = blockIdx.x;
    int tid = threadIdx.x;
    if (bid < PREPW_B) {
        int i = bid * 256 + tid;                   // float4 index, 16384 total
        float4 v = reinterpret_cast<const float4*>(W)[i];
        __half2 h0 = __floats2half2_rn(v.x, v.y);
        __half2 h1 = __floats2half2_rn(v.z, v.w);
        reinterpret_cast<__half2*>(g_wh)[2 * i]     = h0;
        reinterpret_cast<__half2*>(g_wh)[2 * i + 1] = h1;
    } else {
        int i = (bid - PREPW_B) * 256 + tid;       // 8-half chunk
        const float4* xp = reinterpret_cast<const float4*>(X) + 2 * (size_t)i;
        float4 v0 = __ldg(xp);
        float4 v1 = __ldg(xp + 1);
        __half2 h0 = __floats2half2_rn(v0.x, v0.y);
        __half2 h1 = __floats2half2_rn(v0.z, v0.w);
        __half2 h2 = __floats2half2_rn(v1.x, v1.y);
        __half2 h3 = __floats2half2_rn(v1.z, v1.w);
        uint4 u;
        u.x = *reinterpret_cast<uint32_t*>(&h0);
        u.y = *reinterpret_cast<uint32_t*>(&h1);
        u.z = *reinterpret_cast<uint32_t*>(&h2);
        u.w = *reinterpret_cast<uint32_t*>(&h3);
        reinterpret_cast<uint4*>(g_xh)[i] = u;
    }
}

// ---------------------------------------------------------------------------
// Single-pass decoupled-lookback scan
// ---------------------------------------------------------------------------
__global__ void k_scan_fused() {
    __shared__ int warp_sums[8];
    __shared__ int s_base;
    const int b    = blockIdx.x;
    const int t    = threadIdx.x;
    const int lane = t & 31;
    const int w    = t >> 5;
    const int i    = b * SCAN_B + t;

    int v = (i < N_NODES) ? g_cnt[i] : 0;

    int inc = v;
#pragma unroll
    for (int d = 1; d < 32; d <<= 1) {
        int tt = __shfl_up_sync(0xffffffffu, inc, d);
        if (lane >= d) inc += tt;
    }
    if (lane == 31) warp_sums[w] = inc;
    __syncthreads();
    if (w == 0) {
        int ws = (lane < 8) ? warp_sums[lane] : 0;
#pragma unroll
        for (int d = 1; d < 8; d <<= 1) {
            int tt = __shfl_up_sync(0xffffffffu, ws, d);
            if (lane >= d) ws += tt;
        }
        if (lane < 8) warp_sums[lane] = ws;
    }
    __syncthreads();
    int excl  = inc - v + ((w > 0) ? warp_sums[w - 1] : 0);
    int total = warp_sums[7];

    if (t == 0) {
        if (b == 0) {
            atomicExch(&g_scan_pkt[0], (2ULL << 62) | (unsigned)total);
            s_base = 0;
        } else {
            atomicExch(&g_scan_pkt[b], (1ULL << 62) | (unsigned)total);
            int run = 0;
            int j = b - 1;
            while (true) {
                unsigned long long p;
                while (((p = atomicAdd(&g_scan_pkt[j], 0ULL)) >> 62) == 0) {}
                run += (int)(p & 0xFFFFFFFFULL);
                if ((p >> 62) == 2ULL) break;
                j--;
            }
            atomicExch(&g_scan_pkt[b], (2ULL << 62) | (unsigned)(run + total));
            s_base = run;
        }
    }
    __syncthreads();
    int base = s_base;
    if (i < N_NODES) g_off[i] = base + excl;
    if (i == N_NODES - 1) g_off[N_NODES] = N_EDGES;
}

// ---------------------------------------------------------------------------
// Scatter: atomic-free, position = off[row] + rank
// ---------------------------------------------------------------------------
__global__ __launch_bounds__(256)
void k_scatter(const int*   __restrict__ edge_row,
               const int*   __restrict__ edge_col,
               const float* __restrict__ edge_val) {
    int e = blockIdx.x * blockDim.x + threadIdx.x;
    if (e < N_EDGES) {
        int r = edge_row[e];
        int p = g_off[r] + g_rank[e];
        g_cv[p] = make_int2(edge_col[e], __float_as_int(edge_val[e]));
    }
}

// ---------------------------------------------------------------------------
// GEMM  Y[m,n] = sum_k Xh[m,k]*Wh[n,k]  (fp16 MMA, fp32 acc)
// CTA 128x128, BK=32, 8 warps 4(M) x 2(N), 256 threads, 2 CTAs/SM.
// cp.async THREE-stage pipeline: two tiles in flight (wait_group<2>).
// ---------------------------------------------------------------------------
#define BM 128
#define BN 128
#define BK 32
#define LDS_K 40
#define KTILES (F_DIM / BK)   // 8
#define STAGES 3

__device__ __forceinline__ void mma_f16(float* c, const uint32_t* a, const uint32_t* b) {
    asm volatile(
        "mma.sync.aligned.m16n8k16.row.col.f32.f16.f16.f32 "
        "{%0,%1,%2,%3}, {%4,%5,%6,%7}, {%8,%9}, {%0,%1,%2,%3};"
        : "+f"(c[0]), "+f"(c[1]), "+f"(c[2]), "+f"(c[3])
        : "r"(a[0]), "r"(a[1]), "r"(a[2]), "r"(a[3]), "r"(b[0]), "r"(b[1]));
}

__global__ __launch_bounds__(256, 2)
void gemm_kernel() {
    __shared__ __half As[STAGES][BM][LDS_K];   // 3 x 10 KB
    __shared__ __half Ws[STAGES][BN][LDS_K];   // 3 x 10 KB

    const int t    = threadIdx.x;
    const int lane = t & 31;
    const int wid  = t >> 5;
    const int wm   = wid & 3;
    const int wn   = wid >> 2;
    const int g    = lane >> 2;
    const int tid4 = lane & 3;

    const int m0 = blockIdx.x * BM;
    const int n0 = blockIdx.y * BN;

    int rowS[2], c8S[2];
    const __half* xsrc[2];
    const __half* wsrc[2];
    int xsz[2];
    uint32_t adst[STAGES][2], wdst[STAGES][2];
#pragma unroll
    for (int i = 0; i < 2; i++) {
        int idx = t + i * 256;
        rowS[i] = idx >> 2;
        c8S[i]  = idx & 3;
        int m   = m0 + rowS[i];
        bool ok = (m < N_NODES);
        xsz[i]  = ok ? 16 : 0;
        xsrc[i] = g_xh + (size_t)(ok ? m : 0) * F_DIM + c8S[i] * 8;
        wsrc[i] = g_wh + (size_t)(n0 + rowS[i]) * F_DIM + c8S[i] * 8;
#pragma unroll
        for (int bu = 0; bu < STAGES; bu++) {
            adst[bu][i] = (uint32_t)__cvta_generic_to_shared(&As[bu][rowS[i]][c8S[i] * 8]);
            wdst[bu][i] = (uint32_t)__cvta_generic_to_shared(&Ws[bu][rowS[i]][c8S[i] * 8]);
        }
    }

    // prologue: issue tiles 0, 1, 2
#pragma unroll
    for (int kt = 0; kt < STAGES; kt++) {
        int koff = kt * BK;
#pragma unroll
        for (int i = 0; i < 2; i++) {
            cp_async16(adst[kt][i], xsrc[i] + koff, xsz[i]);
            cp_async16(wdst[kt][i], wsrc[i] + koff, 16);
        }
        cp_commit();
    }

    float acc[2][8][4];
#pragma unroll
    for (int i = 0; i < 2; i++)
#pragma unroll
        for (int j = 0; j < 8; j++)
#pragma unroll
            for (int k = 0; k < 4; k++) acc[i][j][k] = 0.f;

#pragma unroll
    for (int kt = 0; kt < KTILES; kt++) {
        const int buf = kt % STAGES;
        cp_wait<STAGES - 1>();           // tile kt's group complete (2 in flight)
        __syncthreads();

#pragma unroll
        for (int ks = 0; ks < 2; ks++) {
            int kb = ks * 16;
            uint32_t a[2][4];
#pragma unroll
            for (int mi = 0; mi < 2; mi++) {
                int r = wm * 32 + mi * 16;
                a[mi][0] = *reinterpret_cast<const uint32_t*>(&As[buf][r + g    ][kb + 2 * tid4]);
                a[mi][1] = *reinterpret_cast<const uint32_t*>(&As[buf][r + g + 8][kb + 2 * tid4]);
                a[mi][2] = *reinterpret_cast<const uint32_t*>(&As[buf][r + g    ][kb + 2 * tid4 + 8]);
                a[mi][3] = *reinterpret_cast<const uint32_t*>(&As[buf][r + g + 8][kb + 2 * tid4 + 8]);
            }
            uint32_t b[8][2];
#pragma unroll
            for (int ni = 0; ni < 8; ni++) {
                int n = wn * 64 + ni * 8 + g;
                b[ni][0] = *reinterpret_cast<const uint32_t*>(&Ws[buf][n][kb + 2 * tid4]);
                b[ni][1] = *reinterpret_cast<const uint32_t*>(&Ws[buf][n][kb + 2 * tid4 + 8]);
            }
#pragma unroll
            for (int mi = 0; mi < 2; mi++)
#pragma unroll
                for (int ni = 0; ni < 8; ni++)
                    mma_f16(acc[mi][ni], a[mi], b[ni]);
        }
        __syncthreads();                 // all warps done with smem[buf]

        // issue tile kt+STAGES into smem[buf]
        if (kt + STAGES < KTILES) {
            int koff = (kt + STAGES) * BK;
#pragma unroll
            for (int i = 0; i < 2; i++) {
                cp_async16(adst[buf][i], xsrc[i] + koff, xsz[i]);
                cp_async16(wdst[buf][i], wsrc[i] + koff, 16);
            }
            cp_commit();
        } else {
            cp_commit();                 // keep group count in step
        }
    }

    // store Y as fp16
#pragma unroll
    for (int mi = 0; mi < 2; mi++) {
        int r_base = m0 + wm * 32 + mi * 16;
#pragma unroll
        for (int ni = 0; ni < 8; ni++) {
            int col = n0 + wn * 64 + ni * 8 + 2 * tid4;
            int r0 = r_base + g;
            int r1 = r_base + g + 8;
            if (r0 < N_NODES) {
                __half2 h = __floats2half2_rn(acc[mi][ni][0], acc[mi][ni][1]);
                *reinterpret_cast<__half2*>(g_yh + (size_t)r0 * F_DIM + col) = h;
            }
            if (r1 < N_NODES) {
                __half2 h = __floats2half2_rn(acc[mi][ni][2], acc[mi][ni][3]);
                *reinterpret_cast<__half2*>(g_yh + (size_t)r1 * F_DIM + col) = h;
            }
        }
    }
}

// ---------------------------------------------------------------------------
// Gather: out[r] = sum_e val_e * Y[col_e] + b.  One warp per row. FFMA2.
// (R13-proven form)
// ---------------------------------------------------------------------------
__device__ __forceinline__ void fma8_x2(unsigned long long* acc, uint4 u,
                                        unsigned long long v2) {
    const __half2* h = reinterpret_cast<const __half2*>(&u);
#pragma unroll
    for (int q = 0; q < 4; q++) {
        float2 f = __half22float2(h[q]);
        unsigned long long fu;
        asm("mov.b64 %0, {%1, %2};" : "=l"(fu) : "f"(f.x), "f"(f.y));
        asm("fma.rn.f32x2 %0, %1, %2, %0;" : "+l"(acc[q]) : "l"(fu), "l"(v2));
    }
}

__global__ __launch_bounds__(256, 6)
void k_gather(const float* __restrict__ bias, float* __restrict__ out) {
    int r    = (blockIdx.x * blockDim.x + threadIdx.x) >> 5;
    int lane = threadIdx.x & 31;
    if (r >= N_NODES) return;

    unsigned long long acc[4];
#pragma unroll
    for (int q = 0; q < 4; q++) acc[q] = 0ULL;

    int start = g_off[r];
    int end   = g_off[r + 1];

    for (int base = start; base < end; base += 32) {
        int n = min(32, end - base);
        int   col = 0;
        float val = 0.f;
        if (lane < n) {
            int2 cv = __ldg(&g_cv[base + lane]);
            col = cv.x;
            val = __int_as_float(cv.y);
        }
        int j = 0;
        for (; j + 4 <= n; j += 4) {
            int   c0 = __shfl_sync(0xffffffffu, col, j);
            int   c1 = __shfl_sync(0xffffffffu, col, j + 1);
            int   c2 = __shfl_sync(0xffffffffu, col, j + 2);
            int   c3 = __shfl_sync(0xffffffffu, col, j + 3);
            float v0 = __shfl_sync(0xffffffffu, val, j);
            float v1 = __shfl_sync(0xffffffffu, val, j + 1);
            float v2 = __shfl_sync(0xffffffffu, val, j + 2);
            float v3 = __shfl_sync(0xffffffffu, val, j + 3);
            uint4 u0 = __ldg(reinterpret_cast<const uint4*>(g_yh + (size_t)c0 * F_DIM) + lane);
            uint4 u1 = __ldg(reinterpret_cast<const uint4*>(g_yh + (size_t)c1 * F_DIM) + lane);
            uint4 u2 = __ldg(reinterpret_cast<const uint4*>(g_yh + (size_t)c2 * F_DIM) + lane);
            uint4 u3 = __ldg(reinterpret_cast<const uint4*>(g_yh + (size_t)c3 * F_DIM) + lane);
            unsigned long long p0, p1, p2, p3;
            asm("mov.b64 %0, {%1, %1};" : "=l"(p0) : "f"(v0));
            asm("mov.b64 %0, {%1, %1};" : "=l"(p1) : "f"(v1));
            asm("mov.b64 %0, {%1, %1};" : "=l"(p2) : "f"(v2));
            asm("mov.b64 %0, {%1, %1};" : "=l"(p3) : "f"(v3));
            fma8_x2(acc, u0, p0);
            fma8_x2(acc, u1, p1);
            fma8_x2(acc, u2, p2);
            fma8_x2(acc, u3, p3);
        }
        for (; j < n; j++) {
            int   c = __shfl_sync(0xffffffffu, col, j);
            float v = __shfl_sync(0xffffffffu, val, j);
            uint4 u = __ldg(reinterpret_cast<const uint4*>(g_yh + (size_t)c * F_DIM) + lane);
            unsigned long long p;
            asm("mov.b64 %0, {%1, %1};" : "=l"(p) : "f"(v));
            fma8_x2(acc, u, p);
        }
    }

    float a[8];
#pragma unroll
    for (int q = 0; q < 4; q++) {
        float lo, hi;
        asm("mov.b64 {%0, %1}, %2;" : "=f"(lo), "=f"(hi) : "l"(acc[q]));
        a[2 * q]     = lo;
        a[2 * q + 1] = hi;
    }
    const float4* bp = reinterpret_cast<const float4*>(bias + lane * 8);
    float4 b0 = __ldg(bp);
    float4 b1 = __ldg(bp + 1);
    float4 o0 = make_float4(a[0] + b0.x, a[1] + b0.y, a[2] + b0.z, a[3] + b0.w);
    float4 o1 = make_float4(a[4] + b1.x, a[5] + b1.y, a[6] + b1.z, a[7] + b1.w);
    float4* orow = reinterpret_cast<float4*>(out + (size_t)r * F_DIM + lane * 8);
    orow[0] = o0;
    orow[1] = o1;
}

// ---------------------------------------------------------------------------
// Launch: fork/join two independent chains (R13-proven structure)
//   chain A (default stream): memsets -> hist -> scan -> scatter
//   chain B (s2):             prep(W,X) -> gemm
//   join -> gather
// ---------------------------------------------------------------------------
extern "C" void kernel_launch(void* const* d_in, const int* in_sizes, int n_in,
                              void* d_out, int out_size) {
    const float* x        = (const float*)d_in[0];
    const int*   edge_row = (const int*)  d_in[1];
    const int*   edge_col = (const int*)  d_in[2];
    const float* edge_val = (const float*)d_in[3];
    const float* W        = (const float*)d_in[4];
    const float* b        = (const float*)d_in[5];
    float*       out      = (float*)d_out;

    static cudaStream_t s2 = nullptr;
    static cudaEvent_t  ev_fork = nullptr, ev_join = nullptr;
    if (s2 == nullptr) {
        cudaStreamCreateWithFlags(&s2, cudaStreamNonBlocking);
        cudaEventCreateWithFlags(&ev_fork, cudaEventDisableTiming);
        cudaEventCreateWithFlags(&ev_join, cudaEventDisableTiming);
    }

    // ---- fork ----
    cudaEventRecord(ev_fork, 0);
    cudaStreamWaitEvent(s2, ev_fork, 0);

    // ---- chain A: CSR build (default stream) ----
    void* cnt_ptr = nullptr;
    cudaGetSymbolAddress(&cnt_ptr, g_cnt);
    cudaMemsetAsync(cnt_ptr, 0, N_NODES * sizeof(int));
    void* pkt_ptr = nullptr;
    cudaGetSymbolAddress(&pkt_ptr, g_scan_pkt);
    cudaMemsetAsync(pkt_ptr, 0, SCAN_NB * sizeof(unsigned long long));
    k_hist<<<(N_EDGES + 255) / 256, 256>>>(edge_row);
    k_scan_fused<<<SCAN_NB, SCAN_B>>>();
    k_scatter<<<(N_EDGES + 255) / 256, 256>>>(edge_row, edge_col, edge_val);

    // ---- chain B: prep + GEMM (s2) ----
    k_prep<<<PREP_BLOCKS, 256, 0, s2>>>(W, x);
    {
        dim3 grid(PAD_M / BM, F_DIM / BN);   // 391 x 2
        gemm_kernel<<<grid, 256, 0, s2>>>();
    }

    // ---- join ----
    cudaEventRecord(ev_join, s2);
    cudaStreamWaitEvent(0, ev_join, 0);

    // ---- gather (needs scatter + gemm) ----
    k_gather<<<(N_NODES * 32 + 255) / 256, 256>>>(b, out);
}